// round 6
// baseline (speedup 1.0000x reference)
#include <cuda_runtime.h>
#include <math.h>

// Problem-fixed dimensions
#define NNODES 100000
#define NEDGES 1600000
#define CIN 64
#define CH 128
#define GROWS 64         // rows per block in GEMM kernels (tail-guarded)
#define KFIN 384         // final projection K

// Scratch (__device__ globals; no allocation allowed)
__device__ __align__(128) float g_bufA[(size_t)NNODES * CH];
__device__ __align__(128) float g_bufB[(size_t)NNODES * CH];
__device__ __align__(128) float g_dinv[NNODES];
__device__ __align__(128) float g_stats[4 * CH];       // [sum1|sq1|sum2|sq2]
__device__ __align__(128) int   g_rowptr[NNODES + 1];
__device__ __align__(128) int   g_cursor[NNODES];
__device__ __align__(128) unsigned long long g_csr[NEDGES];  // (norm<<32)|src
__device__ __align__(128) float g_Wp1[CIN * CH];       // k-packed weights
__device__ __align__(128) float g_Wp2[CH * CH];
__device__ __align__(128) float g_Wpm[KFIN * CH];
__device__ __align__(128) int   g_part[256];           // scan partials
__device__ int g_idx32;

#define SCAN_BLOCKS 196
#define SCAN_BT 512

// ---------------------------------------------------------------------------
typedef unsigned long long ull;

__device__ __forceinline__ ull ffma2(ull a, ull b, ull c) {
    ull d;
    asm("fma.rn.f32x2 %0, %1, %2, %3;" : "=l"(d) : "l"(a), "l"(b), "l"(c));
    return d;
}
__device__ __forceinline__ float unpack_sum(ull a) {
    float lo, hi;
    asm("mov.b64 {%0, %1}, %2;" : "=f"(lo), "=f"(hi) : "l"(a));
    return lo + hi;
}
__device__ __forceinline__ void csr_get(ull e, int& src, float& norm) {
    src = (int)(unsigned)(e & 0xFFFFFFFFull);
    norm = __uint_as_float((unsigned)(e >> 32));
}

// ---------------------------------------------------------------------------
__global__ void detect_idx_kernel(const int* __restrict__ ei) {
    __shared__ int s_any;
    if (threadIdx.x == 0) s_any = 0;
    __syncthreads();
    int any = 0;
    for (int i = 1 + 2 * threadIdx.x; i < 4096; i += 2 * blockDim.x) any |= ei[i];
    if (any) atomicOr(&s_any, 1);
    __syncthreads();
    if (threadIdx.x == 0) g_idx32 = (s_any != 0) ? 1 : 0;
}

__device__ __forceinline__ void load_edge(const void* ei, int e, int& src, int& dst) {
    if (g_idx32) {
        const int* p = (const int*)ei;
        src = p[e];
        dst = p[NEDGES + e];
    } else {
        const long long* p = (const long long*)ei;
        src = (int)p[e];
        dst = (int)p[NEDGES + e];
    }
}

__global__ void deg_init_kernel() {
    int i = blockIdx.x * blockDim.x + threadIdx.x;
    if (i < NNODES) {
        g_dinv[i] = 1.0f;
        g_cursor[i] = 0;
    }
    if (i < 4 * CH) g_stats[i] = 0.0f;
}

__global__ void deg_count_kernel(const void* __restrict__ ei,
                                 const float* __restrict__ ew) {
    int e = blockIdx.x * blockDim.x + threadIdx.x;
    if (e >= NEDGES) return;
    int src, dst;
    load_edge(ei, e, src, dst);
    atomicAdd(&g_dinv[dst], ew[e]);
    atomicAdd(&g_cursor[dst], 1);
}

// ---------------------------------------------------------------------------
// 3-phase multi-block scan of counts -> rowptr/cursor; also dinv = rsqrt(deg).
// ---------------------------------------------------------------------------
__global__ __launch_bounds__(SCAN_BT) void scanA_kernel() {
    __shared__ int ssum[SCAN_BT];
    int i = blockIdx.x * SCAN_BT + threadIdx.x;
    int c = (i < NNODES) ? g_cursor[i] : 0;
    if (i < NNODES) g_dinv[i] = rsqrtf(g_dinv[i]);
    ssum[threadIdx.x] = c;
    __syncthreads();
    for (int off = 1; off < SCAN_BT; off <<= 1) {
        int v = (threadIdx.x >= off) ? ssum[threadIdx.x - off] : 0;
        __syncthreads();
        ssum[threadIdx.x] += v;
        __syncthreads();
    }
    if (i < NNODES) g_rowptr[i] = ssum[threadIdx.x];
    if (threadIdx.x == SCAN_BT - 1) g_part[blockIdx.x] = ssum[threadIdx.x];
}

__global__ __launch_bounds__(256) void scanB_kernel() {
    __shared__ int ssum[256];
    int t = threadIdx.x;
    ssum[t] = (t < SCAN_BLOCKS) ? g_part[t] : 0;
    __syncthreads();
    for (int off = 1; off < 256; off <<= 1) {
        int v = (t >= off) ? ssum[t - off] : 0;
        __syncthreads();
        ssum[t] += v;
        __syncthreads();
    }
    g_part[t] = (t == 0) ? 0 : ssum[t - 1];
    if (t == 255) g_rowptr[NNODES] = ssum[255];
}

__global__ __launch_bounds__(SCAN_BT) void scanC_kernel() {
    int i = blockIdx.x * SCAN_BT + threadIdx.x;
    if (i >= NNODES) return;
    int off = g_part[blockIdx.x];
    int excl = g_rowptr[i] + off - g_cursor[i];
    g_rowptr[i] = excl;
    g_cursor[i] = excl;
}

__global__ void fill_kernel(const void* __restrict__ ei,
                            const float* __restrict__ ew) {
    int e = blockIdx.x * blockDim.x + threadIdx.x;
    if (e >= NEDGES) return;
    int src, dst;
    load_edge(ei, e, src, dst);
    float norm = g_dinv[src] * ew[e] * g_dinv[dst];
    int pos = atomicAdd(&g_cursor[dst], 1);
    g_csr[pos] = ((ull)__float_as_uint(norm) << 32) | (unsigned)src;
}

// ---------------------------------------------------------------------------
__global__ void pack_kernel(const float* __restrict__ W1,
                            const float* __restrict__ W2,
                            const float* __restrict__ Wm) {
    const int n1 = (CIN / 4) * CH;
    const int n2 = (CH / 4) * CH;
    const int n3 = (KFIN / 4) * CH;
    for (int idx = blockIdx.x * blockDim.x + threadIdx.x; idx < n1 + n2 + n3;
         idx += gridDim.x * blockDim.x) {
        const float* W;
        float* Wp;
        int i = idx;
        if (i < n1)      { W = W1; Wp = g_Wp1; }
        else if (i < n1 + n2) { W = W2; Wp = g_Wp2; i -= n1; }
        else             { W = Wm; Wp = g_Wpm; i -= n1 + n2; }
        int kp2 = i / CH, c = i % CH;
        float4 v;
        v.x = W[(4 * kp2 + 0) * CH + c];
        v.y = W[(4 * kp2 + 1) * CH + c];
        v.z = W[(4 * kp2 + 2) * CH + c];
        v.w = W[(4 * kp2 + 3) * CH + c];
        ((float4*)Wp)[i] = v;
    }
}

// ---------------------------------------------------------------------------
// Aggregation of 64-channel x (layer 1). 2 nodes/warp, 4-wide unroll.
// ---------------------------------------------------------------------------
__global__ __launch_bounds__(256) void agg64_kernel(const float* __restrict__ x,
                                                    float* __restrict__ out) {
    int warp = (blockIdx.x * blockDim.x + threadIdx.x) >> 5;
    int lane = threadIdx.x & 31;
    int node = warp * 2 + (lane >> 4);
    int l16 = lane & 15;
    if (node >= NNODES) return;
    const float4* x4 = (const float4*)x;

    float di = g_dinv[node];
    float s = di * di;
    float4 hv = x4[(size_t)node * 16 + l16];
    float4 acc = make_float4(s * hv.x, s * hv.y, s * hv.z, s * hv.w);

    int j = g_rowptr[node];
    int end = g_rowptr[node + 1];
    for (; j + 3 < end; j += 4) {
        int s0, s1, s2, s3;
        float n0, n1, n2, n3;
        csr_get(g_csr[j], s0, n0);
        csr_get(g_csr[j + 1], s1, n1);
        csr_get(g_csr[j + 2], s2, n2);
        csr_get(g_csr[j + 3], s3, n3);
        float4 v0 = x4[(size_t)s0 * 16 + l16];
        float4 v1 = x4[(size_t)s1 * 16 + l16];
        float4 v2 = x4[(size_t)s2 * 16 + l16];
        float4 v3 = x4[(size_t)s3 * 16 + l16];
        acc.x += n0 * v0.x + n1 * v1.x + n2 * v2.x + n3 * v3.x;
        acc.y += n0 * v0.y + n1 * v1.y + n2 * v2.y + n3 * v3.y;
        acc.z += n0 * v0.z + n1 * v1.z + n2 * v2.z + n3 * v3.z;
        acc.w += n0 * v0.w + n1 * v1.w + n2 * v2.w + n3 * v3.w;
    }
    for (; j < end; j++) {
        int s0;
        float n0;
        csr_get(g_csr[j], s0, n0);
        float4 v0 = x4[(size_t)s0 * 16 + l16];
        acc.x += n0 * v0.x;
        acc.y += n0 * v0.y;
        acc.z += n0 * v0.z;
        acc.w += n0 * v0.w;
    }
    ((float4*)out)[(size_t)node * 16 + l16] = acc;
}

// ---------------------------------------------------------------------------
// Aggregation of 128-channel h1 with BN1+ReLU on the fly. Warp per node.
// ---------------------------------------------------------------------------
__global__ __launch_bounds__(256) void agg_bn_kernel(const float* __restrict__ h,
                                                     const float* __restrict__ gamma,
                                                     const float* __restrict__ beta,
                                                     float* __restrict__ out) {
    __shared__ float sc[CH], sh[CH];
    if (threadIdx.x < CH) {
        int c = threadIdx.x;
        float mean = g_stats[c] * (1.0f / NNODES);
        float var = g_stats[CH + c] * (1.0f / NNODES) - mean * mean;
        float scale = gamma[c] * rsqrtf(var + 1e-5f);
        sc[c] = scale;
        sh[c] = beta[c] - mean * scale;
    }
    __syncthreads();

    int node = (blockIdx.x * blockDim.x + threadIdx.x) >> 5;
    int lane = threadIdx.x & 31;
    if (node >= NNODES) return;
    const float4* h4 = (const float4*)h;
    float4 scv = *(const float4*)&sc[lane * 4];
    float4 shv = *(const float4*)&sh[lane * 4];

    float di = g_dinv[node];
    float s = di * di;
    float4 hv = h4[(size_t)node * 32 + lane];
    float4 acc;
    acc.x = s * fmaxf(hv.x * scv.x + shv.x, 0.0f);
    acc.y = s * fmaxf(hv.y * scv.y + shv.y, 0.0f);
    acc.z = s * fmaxf(hv.z * scv.z + shv.z, 0.0f);
    acc.w = s * fmaxf(hv.w * scv.w + shv.w, 0.0f);

    int j = g_rowptr[node];
    int end = g_rowptr[node + 1];
    for (; j + 3 < end; j += 4) {
        int s0, s1, s2, s3;
        float n0, n1, n2, n3;
        csr_get(g_csr[j], s0, n0);
        csr_get(g_csr[j + 1], s1, n1);
        csr_get(g_csr[j + 2], s2, n2);
        csr_get(g_csr[j + 3], s3, n3);
        float4 v0 = h4[(size_t)s0 * 32 + lane];
        float4 v1 = h4[(size_t)s1 * 32 + lane];
        float4 v2 = h4[(size_t)s2 * 32 + lane];
        float4 v3 = h4[(size_t)s3 * 32 + lane];
        acc.x += n0 * fmaxf(v0.x * scv.x + shv.x, 0.0f) + n1 * fmaxf(v1.x * scv.x + shv.x, 0.0f)
               + n2 * fmaxf(v2.x * scv.x + shv.x, 0.0f) + n3 * fmaxf(v3.x * scv.x + shv.x, 0.0f);
        acc.y += n0 * fmaxf(v0.y * scv.y + shv.y, 0.0f) + n1 * fmaxf(v1.y * scv.y + shv.y, 0.0f)
               + n2 * fmaxf(v2.y * scv.y + shv.y, 0.0f) + n3 * fmaxf(v3.y * scv.y + shv.y, 0.0f);
        acc.z += n0 * fmaxf(v0.z * scv.z + shv.z, 0.0f) + n1 * fmaxf(v1.z * scv.z + shv.z, 0.0f)
               + n2 * fmaxf(v2.z * scv.z + shv.z, 0.0f) + n3 * fmaxf(v3.z * scv.z + shv.z, 0.0f);
        acc.w += n0 * fmaxf(v0.w * scv.w + shv.w, 0.0f) + n1 * fmaxf(v1.w * scv.w + shv.w, 0.0f)
               + n2 * fmaxf(v2.w * scv.w + shv.w, 0.0f) + n3 * fmaxf(v3.w * scv.w + shv.w, 0.0f);
    }
    for (; j < end; j++) {
        int s0;
        float n0;
        csr_get(g_csr[j], s0, n0);
        float4 v0 = h4[(size_t)s0 * 32 + lane];
        acc.x += n0 * fmaxf(v0.x * scv.x + shv.x, 0.0f);
        acc.y += n0 * fmaxf(v0.y * scv.y + shv.y, 0.0f);
        acc.z += n0 * fmaxf(v0.z * scv.z + shv.z, 0.0f);
        acc.w += n0 * fmaxf(v0.w * scv.w + shv.w, 0.0f);
    }
    ((float4*)out)[(size_t)node * 32 + lane] = acc;
}

// ---------------------------------------------------------------------------
// GEMM: 256 threads, 64 rows/block (tail-guarded), 2-col thread tile.
// Thread: c = tid&63 -> cols (c, c+64); g = tid>>6 -> rows [g*16, g*16+16).
// ---------------------------------------------------------------------------
template <int K>
__global__ __launch_bounds__(256) void gemm_kernel(const float* __restrict__ A,
                                                   const float* __restrict__ Wp,
                                                   const float* __restrict__ b,
                                                   float* __restrict__ C,
                                                   float* __restrict__ stats) {
    __shared__ float xs[GROWS][K];
    const int row0 = blockIdx.x * GROWS;
    const int tid = threadIdx.x;
    const int c = tid & 63;
    const int g = tid >> 6;            // 0..3

    float4* xs4 = (float4*)&xs[0][0];
    if (row0 + GROWS <= NNODES) {
        const float4* A4 = (const float4*)(A + (size_t)row0 * K);
#pragma unroll
        for (int i = tid; i < GROWS * K / 4; i += 256) xs4[i] = A4[i];
    } else {
        const float4* A4 = (const float4*)A;
#pragma unroll 1
        for (int i = tid; i < GROWS * K / 4; i += 256) {
            int r = i / (K / 4);
            int c4 = i % (K / 4);
            int row = min(row0 + r, NNODES - 1);
            xs4[i] = A4[(size_t)row * (K / 4) + c4];
        }
    }
    __syncthreads();

    ull acc0[16], acc1[16];
#pragma unroll
    for (int r = 0; r < 16; r++) { acc0[r] = 0ULL; acc1[r] = 0ULL; }

    const ulonglong2* Wp2 = (const ulonglong2*)Wp;
#pragma unroll 2
    for (int kp2 = 0; kp2 < K / 4; kp2++) {
        ulonglong2 w0 = Wp2[kp2 * CH + c];
        ulonglong2 w1 = Wp2[kp2 * CH + c + 64];
#pragma unroll
        for (int r = 0; r < 16; r++) {
            ulonglong2 xv = *(const ulonglong2*)&xs[g * 16 + r][4 * kp2];
            acc0[r] = ffma2(xv.x, w0.x, acc0[r]);
            acc0[r] = ffma2(xv.y, w0.y, acc0[r]);
            acc1[r] = ffma2(xv.x, w1.x, acc1[r]);
            acc1[r] = ffma2(xv.y, w1.y, acc1[r]);
        }
    }

    float b0 = b[c], b1 = b[c + 64];
    float s0 = 0.0f, q0 = 0.0f, s1 = 0.0f, q1 = 0.0f;
    const int rbase = row0 + g * 16;
#pragma unroll
    for (int r = 0; r < 16; r++) {
        if (rbase + r < NNODES) {
            float v0 = unpack_sum(acc0[r]) + b0;
            float v1 = unpack_sum(acc1[r]) + b1;
            C[(size_t)(rbase + r) * CH + c] = v0;
            C[(size_t)(rbase + r) * CH + c + 64] = v1;
            s0 += v0; q0 += v0 * v0;
            s1 += v1; q1 += v1 * v1;
        }
    }
    atomicAdd(&stats[c], s0);
    atomicAdd(&stats[CH + c], q0);
    atomicAdd(&stats[c + 64], s1);
    atomicAdd(&stats[CH + c + 64], q1);
}

// ---------------------------------------------------------------------------
// Final fused layer: 256 threads, 64 rows/block (tail-guarded), dynamic smem.
// ---------------------------------------------------------------------------
__global__ __launch_bounds__(256) void final_kernel(const float* __restrict__ h,
                                                    const float* __restrict__ dist,
                                                    const float* __restrict__ degf,
                                                    const float* __restrict__ Wd,
                                                    const float* __restrict__ bd,
                                                    const float* __restrict__ Wg,
                                                    const float* __restrict__ bg,
                                                    const float* __restrict__ Wp,
                                                    const float* __restrict__ bm,
                                                    const float* __restrict__ gamma,
                                                    const float* __restrict__ beta,
                                                    float* __restrict__ out) {
    extern __shared__ float smem[];
    float* cs = smem;                       // [GROWS][KFIN]
    float* sc = smem + GROWS * KFIN;
    float* sh = sc + CH;
    const int row0 = blockIdx.x * GROWS;
    const int tid = threadIdx.x;
    const int c = tid & 63;
    const int g = tid >> 6;

    if (tid < CH) {
        float mean = g_stats[2 * CH + tid] * (1.0f / NNODES);
        float var = g_stats[3 * CH + tid] * (1.0f / NNODES) - mean * mean;
        float scale = gamma[tid] * rsqrtf(var + 1e-5f);
        sc[tid] = scale;
        sh[tid] = beta[tid] - mean * scale;
    }
    __syncthreads();

    const float4* h4 = (const float4*)h;
#pragma unroll 1
    for (int i = tid; i < GROWS * CH / 4; i += 256) {
        int r = i >> 5;
        int cc = (i & 31) * 4;
        int row = min(row0 + r, NNODES - 1);
        float4 v = h4[(size_t)row * 32 + (i & 31)];
        float4 scv = *(const float4*)&sc[cc];
        float4 shv = *(const float4*)&sh[cc];
        v.x = fmaxf(v.x * scv.x + shv.x, 0.0f);
        v.y = fmaxf(v.y * scv.y + shv.y, 0.0f);
        v.z = fmaxf(v.z * scv.z + shv.z, 0.0f);
        v.w = fmaxf(v.w * scv.w + shv.w, 0.0f);
        *(float4*)&cs[r * KFIN + cc] = v;
    }
    if (tid < 128) {
        float wd = Wd[tid], bdv = bd[tid];
#pragma unroll 4
        for (int r = 0; r < GROWS; r++) {
            int row = min(row0 + r, NNODES - 1);
            cs[r * KFIN + CH + tid] = fmaxf(dist[row] * wd + bdv, 0.0f);
        }
    } else {
        int c2 = tid - 128;
        float wg = Wg[c2], bgv = bg[c2];
#pragma unroll 4
        for (int r = 0; r < GROWS; r++) {
            int row = min(row0 + r, NNODES - 1);
            cs[r * KFIN + 2 * CH + c2] = fmaxf(degf[row] * wg + bgv, 0.0f);
        }
    }
    __syncthreads();

    ull acc0[16], acc1[16];
#pragma unroll
    for (int r = 0; r < 16; r++) { acc0[r] = 0ULL; acc1[r] = 0ULL; }

    const ulonglong2* Wp2 = (const ulonglong2*)Wp;
#pragma unroll 2
    for (int kp2 = 0; kp2 < KFIN / 4; kp2++) {
        ulonglong2 w0 = Wp2[kp2 * CH + c];
        ulonglong2 w1 = Wp2[kp2 * CH + c + 64];
        const char* xbase = (const char*)&cs[(g * 16) * KFIN + 4 * kp2];
#pragma unroll
        for (int r = 0; r < 16; r++) {
            ulonglong2 xv = *(const ulonglong2*)(xbase + (size_t)r * KFIN * 4);
            acc0[r] = ffma2(xv.x, w0.x, acc0[r]);
            acc0[r] = ffma2(xv.y, w0.y, acc0[r]);
            acc1[r] = ffma2(xv.x, w1.x, acc1[r]);
            acc1[r] = ffma2(xv.y, w1.y, acc1[r]);
        }
    }

    float b0 = bm[c], b1 = bm[c + 64];
    const int rbase = row0 + g * 16;
#pragma unroll
    for (int r = 0; r < 16; r++) {
        if (rbase + r < NNODES) {
            out[(size_t)(rbase + r) * CH + c] = unpack_sum(acc0[r]) + b0;
            out[(size_t)(rbase + r) * CH + c + 64] = unpack_sum(acc1[r]) + b1;
        }
    }
}

// ---------------------------------------------------------------------------
extern "C" void kernel_launch(void* const* d_in, const int* in_sizes, int n_in,
                              void* d_out, int out_size) {
    const float* x     = (const float*)d_in[0];
    const void*  ei    = d_in[1];
    const float* ew    = (const float*)d_in[2];
    const float* dist  = (const float*)d_in[3];
    const float* degf  = (const float*)d_in[4];
    const float* W1    = (const float*)d_in[5];
    const float* b1    = (const float*)d_in[6];
    const float* W2    = (const float*)d_in[7];
    const float* b2    = (const float*)d_in[8];
    const float* g1    = (const float*)d_in[9];
    const float* be1   = (const float*)d_in[10];
    const float* g2    = (const float*)d_in[11];
    const float* be2   = (const float*)d_in[12];
    const float* Wd    = (const float*)d_in[13];
    const float* bd    = (const float*)d_in[14];
    const float* Wg    = (const float*)d_in[15];
    const float* bg    = (const float*)d_in[16];
    const float* Wm    = (const float*)d_in[17];
    const float* bm    = (const float*)d_in[18];
    float* out = (float*)d_out;

    float *bufA, *bufB, *stats, *Wp1, *Wp2, *Wpm;
    cudaGetSymbolAddress((void**)&bufA, g_bufA);
    cudaGetSymbolAddress((void**)&bufB, g_bufB);
    cudaGetSymbolAddress((void**)&stats, g_stats);
    cudaGetSymbolAddress((void**)&Wp1, g_Wp1);
    cudaGetSymbolAddress((void**)&Wp2, g_Wp2);
    cudaGetSymbolAddress((void**)&Wpm, g_Wpm);

    const int nodeBlocks = (NNODES + 255) / 256;
    const int edgeBlocks = (NEDGES + 255) / 256;
    const int gemmBlocks = (NNODES + GROWS - 1) / GROWS;   // 1563
    const int agg128Blocks = (NNODES * 32 + 255) / 256;
    const int agg64Blocks  = ((NNODES + 1) / 2 * 32 + 255) / 256;
    const int FIN_SMEM = (GROWS * KFIN + 2 * CH) * 4;      // 99328 B

    cudaFuncSetAttribute(final_kernel, cudaFuncAttributeMaxDynamicSharedMemorySize, FIN_SMEM);

    // slots 1-3
    detect_idx_kernel<<<1, 256>>>((const int*)ei);
    deg_init_kernel<<<nodeBlocks, 256>>>();
    pack_kernel<<<160, 256>>>(W1, W2, Wm);

    // slot 4: ncu PROBE of agg_bn_kernel (grid-limited; bufA overwritten later)
    agg_bn_kernel<<<300, 256>>>(bufB, g1, be1, bufA);

    // --- gcn_norm + CSR build ---
    deg_count_kernel<<<edgeBlocks, 256>>>(ei, ew);
    scanA_kernel<<<SCAN_BLOCKS, SCAN_BT>>>();
    scanB_kernel<<<1, 256>>>();
    scanC_kernel<<<SCAN_BLOCKS, SCAN_BT>>>();
    fill_kernel<<<edgeBlocks, 256>>>(ei, ew);

    // --- layer 1 ---
    agg64_kernel<<<agg64Blocks, 256>>>(x, bufA);
    gemm_kernel<CIN><<<gemmBlocks, 256>>>(bufA, Wp1, b1, bufB, stats);

    // --- layer 2 ---
    agg_bn_kernel<<<agg128Blocks, 256>>>(bufB, g1, be1, bufA);
    gemm_kernel<CH><<<gemmBlocks, 256>>>(bufA, Wp2, b2, bufB, stats + 2 * CH);

    // --- final ---
    final_kernel<<<gemmBlocks, 256, FIN_SMEM>>>(bufB, dist, degf, Wd, bd, Wg, bg,
                                                Wpm, bm, g2, be2, out);
}

// round 7
// speedup vs baseline: 1.2482x; 1.2482x over previous
#include <cuda_runtime.h>
#include <math.h>

// Problem-fixed dimensions
#define NNODES 100000
#define NEDGES 1600000
#define CIN 64
#define CH 128
#define GROWS 64         // rows per block in GEMM kernels (tail-guarded)
#define KFIN 384         // final projection K
#define KS 388           // padded smem row stride for final (bank-conflict-free frags)

// Scratch (__device__ globals; no allocation allowed)
__device__ __align__(128) float g_bufA[(size_t)NNODES * CH];
__device__ __align__(128) float g_bufB[(size_t)NNODES * CH];
__device__ __align__(128) float g_dinv[NNODES];
__device__ __align__(128) float g_stats[4 * CH];       // [sum1|sq1|sum2|sq2]
__device__ __align__(128) int   g_rowptr[NNODES + 1];
__device__ __align__(128) int   g_cursor[NNODES];
__device__ __align__(128) unsigned long long g_csr[NEDGES];  // (norm<<32)|src
__device__ __align__(128) float g_Wp1[CIN * CH];       // k-packed weights (fp32 path)
__device__ __align__(128) float g_Wp2[CH * CH];
__device__ __align__(128) unsigned g_Wtc[KFIN * CH];   // tf32 B-fragment-packed Wm
__device__ __align__(128) int   g_part[256];           // scan partials
__device__ int g_idx32;

#define SCAN_BLOCKS 196
#define SCAN_BT 512

// ---------------------------------------------------------------------------
typedef unsigned long long ull;

__device__ __forceinline__ ull ffma2(ull a, ull b, ull c) {
    ull d;
    asm("fma.rn.f32x2 %0, %1, %2, %3;" : "=l"(d) : "l"(a), "l"(b), "l"(c));
    return d;
}
__device__ __forceinline__ float unpack_sum(ull a) {
    float lo, hi;
    asm("mov.b64 {%0, %1}, %2;" : "=f"(lo), "=f"(hi) : "l"(a));
    return lo + hi;
}
__device__ __forceinline__ void csr_get(ull e, int& src, float& norm) {
    src = (int)(unsigned)(e & 0xFFFFFFFFull);
    norm = __uint_as_float((unsigned)(e >> 32));
}
__device__ __forceinline__ unsigned cvt_tf32(float f) {
    unsigned u;
    asm("cvt.rna.tf32.f32 %0, %1;" : "=r"(u) : "f"(f));
    return u;
}
__device__ __forceinline__ void mma_tf32(float* d, unsigned a0, unsigned a1,
                                         unsigned a2, unsigned a3,
                                         unsigned b0, unsigned b1) {
    asm("mma.sync.aligned.m16n8k8.row.col.f32.tf32.tf32.f32 "
        "{%0,%1,%2,%3},{%4,%5,%6,%7},{%8,%9},{%0,%1,%2,%3};"
        : "+f"(d[0]), "+f"(d[1]), "+f"(d[2]), "+f"(d[3])
        : "r"(a0), "r"(a1), "r"(a2), "r"(a3), "r"(b0), "r"(b1));
}

// ---------------------------------------------------------------------------
__global__ void detect_idx_kernel(const int* __restrict__ ei) {
    __shared__ int s_any;
    if (threadIdx.x == 0) s_any = 0;
    __syncthreads();
    int any = 0;
    for (int i = 1 + 2 * threadIdx.x; i < 4096; i += 2 * blockDim.x) any |= ei[i];
    if (any) atomicOr(&s_any, 1);
    __syncthreads();
    if (threadIdx.x == 0) g_idx32 = (s_any != 0) ? 1 : 0;
}

__device__ __forceinline__ void load_edge(const void* ei, int e, int& src, int& dst) {
    if (g_idx32) {
        const int* p = (const int*)ei;
        src = p[e];
        dst = p[NEDGES + e];
    } else {
        const long long* p = (const long long*)ei;
        src = (int)p[e];
        dst = (int)p[NEDGES + e];
    }
}

__global__ void deg_init_kernel() {
    int i = blockIdx.x * blockDim.x + threadIdx.x;
    if (i < NNODES) {
        g_dinv[i] = 1.0f;
        g_cursor[i] = 0;
    }
    if (i < 4 * CH) g_stats[i] = 0.0f;
}

__global__ void deg_count_kernel(const void* __restrict__ ei,
                                 const float* __restrict__ ew) {
    int e = blockIdx.x * blockDim.x + threadIdx.x;
    if (e >= NEDGES) return;
    int src, dst;
    load_edge(ei, e, src, dst);
    atomicAdd(&g_dinv[dst], ew[e]);
    atomicAdd(&g_cursor[dst], 1);
}

// ---------------------------------------------------------------------------
// 3-phase multi-block scan of counts -> rowptr/cursor; also dinv = rsqrt(deg).
// ---------------------------------------------------------------------------
__global__ __launch_bounds__(SCAN_BT) void scanA_kernel() {
    __shared__ int ssum[SCAN_BT];
    int i = blockIdx.x * SCAN_BT + threadIdx.x;
    int c = (i < NNODES) ? g_cursor[i] : 0;
    if (i < NNODES) g_dinv[i] = rsqrtf(g_dinv[i]);
    ssum[threadIdx.x] = c;
    __syncthreads();
    for (int off = 1; off < SCAN_BT; off <<= 1) {
        int v = (threadIdx.x >= off) ? ssum[threadIdx.x - off] : 0;
        __syncthreads();
        ssum[threadIdx.x] += v;
        __syncthreads();
    }
    if (i < NNODES) g_rowptr[i] = ssum[threadIdx.x];
    if (threadIdx.x == SCAN_BT - 1) g_part[blockIdx.x] = ssum[threadIdx.x];
}

__global__ __launch_bounds__(256) void scanB_kernel() {
    __shared__ int ssum[256];
    int t = threadIdx.x;
    ssum[t] = (t < SCAN_BLOCKS) ? g_part[t] : 0;
    __syncthreads();
    for (int off = 1; off < 256; off <<= 1) {
        int v = (t >= off) ? ssum[t - off] : 0;
        __syncthreads();
        ssum[t] += v;
        __syncthreads();
    }
    g_part[t] = (t == 0) ? 0 : ssum[t - 1];
    if (t == 255) g_rowptr[NNODES] = ssum[255];
}

__global__ __launch_bounds__(SCAN_BT) void scanC_kernel() {
    int i = blockIdx.x * SCAN_BT + threadIdx.x;
    if (i >= NNODES) return;
    int off = g_part[blockIdx.x];
    int excl = g_rowptr[i] + off - g_cursor[i];
    g_rowptr[i] = excl;
    g_cursor[i] = excl;
}

__global__ void fill_kernel(const void* __restrict__ ei,
                            const float* __restrict__ ew) {
    int e = blockIdx.x * blockDim.x + threadIdx.x;
    if (e >= NEDGES) return;
    int src, dst;
    load_edge(ei, e, src, dst);
    float norm = g_dinv[src] * ew[e] * g_dinv[dst];
    int pos = atomicAdd(&g_cursor[dst], 1);
    g_csr[pos] = ((ull)__float_as_uint(norm) << 32) | (unsigned)src;
}

// ---------------------------------------------------------------------------
// Pack W1/W2 k-packed (fp32 path); pack Wm into tf32 B-fragment lane order.
// B frag m16n8k8 (col): b0: k=t%4,  n=t/4 ;  b1: k=t%4+4, n=t/4
// Wtc[(kt*16 + nt)*64 + t*2 + e] = tf32(Wm[(kt*8 + t%4 + e*4)*CH + nt*8 + t/4])
// ---------------------------------------------------------------------------
__global__ void pack_kernel(const float* __restrict__ W1,
                            const float* __restrict__ W2,
                            const float* __restrict__ Wm) {
    const int n1 = (CIN / 4) * CH;
    const int n2 = (CH / 4) * CH;
    const int n3 = KFIN * CH;             // Wtc elements (scalar)
    for (int idx = blockIdx.x * blockDim.x + threadIdx.x; idx < n1 + n2 + n3;
         idx += gridDim.x * blockDim.x) {
        int i = idx;
        if (i < n1 + n2) {
            const float* W;
            float* Wp;
            if (i < n1) { W = W1; Wp = g_Wp1; }
            else        { W = W2; Wp = g_Wp2; i -= n1; }
            int kp2 = i / CH, c = i % CH;
            float4 v;
            v.x = W[(4 * kp2 + 0) * CH + c];
            v.y = W[(4 * kp2 + 1) * CH + c];
            v.z = W[(4 * kp2 + 2) * CH + c];
            v.w = W[(4 * kp2 + 3) * CH + c];
            ((float4*)Wp)[i] = v;
        } else {
            i -= n1 + n2;
            int tile = i >> 6;            // (kt*16 + nt)
            int within = i & 63;
            int t = within >> 1;
            int e = within & 1;
            int kt = tile >> 4;
            int nt = tile & 15;
            int k = kt * 8 + (t & 3) + e * 4;
            int n = nt * 8 + (t >> 2);
            g_Wtc[i] = cvt_tf32(Wm[k * CH + n]);
        }
    }
}

// ---------------------------------------------------------------------------
// Aggregation of 64-channel x (layer 1). 2 nodes/warp, 4-wide unroll.
// ---------------------------------------------------------------------------
__global__ __launch_bounds__(256) void agg64_kernel(const float* __restrict__ x,
                                                    float* __restrict__ out) {
    int warp = (blockIdx.x * blockDim.x + threadIdx.x) >> 5;
    int lane = threadIdx.x & 31;
    int node = warp * 2 + (lane >> 4);
    int l16 = lane & 15;
    if (node >= NNODES) return;
    const float4* x4 = (const float4*)x;

    float di = g_dinv[node];
    float s = di * di;
    float4 hv = x4[(size_t)node * 16 + l16];
    float4 acc = make_float4(s * hv.x, s * hv.y, s * hv.z, s * hv.w);

    int j = g_rowptr[node];
    int end = g_rowptr[node + 1];
    for (; j + 3 < end; j += 4) {
        int s0, s1, s2, s3;
        float n0, n1, n2, n3;
        csr_get(g_csr[j], s0, n0);
        csr_get(g_csr[j + 1], s1, n1);
        csr_get(g_csr[j + 2], s2, n2);
        csr_get(g_csr[j + 3], s3, n3);
        float4 v0 = x4[(size_t)s0 * 16 + l16];
        float4 v1 = x4[(size_t)s1 * 16 + l16];
        float4 v2 = x4[(size_t)s2 * 16 + l16];
        float4 v3 = x4[(size_t)s3 * 16 + l16];
        acc.x += n0 * v0.x + n1 * v1.x + n2 * v2.x + n3 * v3.x;
        acc.y += n0 * v0.y + n1 * v1.y + n2 * v2.y + n3 * v3.y;
        acc.z += n0 * v0.z + n1 * v1.z + n2 * v2.z + n3 * v3.z;
        acc.w += n0 * v0.w + n1 * v1.w + n2 * v2.w + n3 * v3.w;
    }
    for (; j < end; j++) {
        int s0;
        float n0;
        csr_get(g_csr[j], s0, n0);
        float4 v0 = x4[(size_t)s0 * 16 + l16];
        acc.x += n0 * v0.x;
        acc.y += n0 * v0.y;
        acc.z += n0 * v0.z;
        acc.w += n0 * v0.w;
    }
    ((float4*)out)[(size_t)node * 16 + l16] = acc;
}

// ---------------------------------------------------------------------------
// Aggregation of 128-channel h1 with BN1+ReLU on the fly. Warp per node.
// ---------------------------------------------------------------------------
__global__ __launch_bounds__(256) void agg_bn_kernel(const float* __restrict__ h,
                                                     const float* __restrict__ gamma,
                                                     const float* __restrict__ beta,
                                                     float* __restrict__ out) {
    __shared__ float sc[CH], sh[CH];
    if (threadIdx.x < CH) {
        int c = threadIdx.x;
        float mean = g_stats[c] * (1.0f / NNODES);
        float var = g_stats[CH + c] * (1.0f / NNODES) - mean * mean;
        float scale = gamma[c] * rsqrtf(var + 1e-5f);
        sc[c] = scale;
        sh[c] = beta[c] - mean * scale;
    }
    __syncthreads();

    int node = (blockIdx.x * blockDim.x + threadIdx.x) >> 5;
    int lane = threadIdx.x & 31;
    if (node >= NNODES) return;
    const float4* h4 = (const float4*)h;
    float4 scv = *(const float4*)&sc[lane * 4];
    float4 shv = *(const float4*)&sh[lane * 4];

    float di = g_dinv[node];
    float s = di * di;
    float4 hv = h4[(size_t)node * 32 + lane];
    float4 acc;
    acc.x = s * fmaxf(hv.x * scv.x + shv.x, 0.0f);
    acc.y = s * fmaxf(hv.y * scv.y + shv.y, 0.0f);
    acc.z = s * fmaxf(hv.z * scv.z + shv.z, 0.0f);
    acc.w = s * fmaxf(hv.w * scv.w + shv.w, 0.0f);

    int j = g_rowptr[node];
    int end = g_rowptr[node + 1];
    for (; j + 3 < end; j += 4) {
        int s0, s1, s2, s3;
        float n0, n1, n2, n3;
        csr_get(g_csr[j], s0, n0);
        csr_get(g_csr[j + 1], s1, n1);
        csr_get(g_csr[j + 2], s2, n2);
        csr_get(g_csr[j + 3], s3, n3);
        float4 v0 = h4[(size_t)s0 * 32 + lane];
        float4 v1 = h4[(size_t)s1 * 32 + lane];
        float4 v2 = h4[(size_t)s2 * 32 + lane];
        float4 v3 = h4[(size_t)s3 * 32 + lane];
        acc.x += n0 * fmaxf(v0.x * scv.x + shv.x, 0.0f) + n1 * fmaxf(v1.x * scv.x + shv.x, 0.0f)
               + n2 * fmaxf(v2.x * scv.x + shv.x, 0.0f) + n3 * fmaxf(v3.x * scv.x + shv.x, 0.0f);
        acc.y += n0 * fmaxf(v0.y * scv.y + shv.y, 0.0f) + n1 * fmaxf(v1.y * scv.y + shv.y, 0.0f)
               + n2 * fmaxf(v2.y * scv.y + shv.y, 0.0f) + n3 * fmaxf(v3.y * scv.y + shv.y, 0.0f);
        acc.z += n0 * fmaxf(v0.z * scv.z + shv.z, 0.0f) + n1 * fmaxf(v1.z * scv.z + shv.z, 0.0f)
               + n2 * fmaxf(v2.z * scv.z + shv.z, 0.0f) + n3 * fmaxf(v3.z * scv.z + shv.z, 0.0f);
        acc.w += n0 * fmaxf(v0.w * scv.w + shv.w, 0.0f) + n1 * fmaxf(v1.w * scv.w + shv.w, 0.0f)
               + n2 * fmaxf(v2.w * scv.w + shv.w, 0.0f) + n3 * fmaxf(v3.w * scv.w + shv.w, 0.0f);
    }
    for (; j < end; j++) {
        int s0;
        float n0;
        csr_get(g_csr[j], s0, n0);
        float4 v0 = h4[(size_t)s0 * 32 + lane];
        acc.x += n0 * fmaxf(v0.x * scv.x + shv.x, 0.0f);
        acc.y += n0 * fmaxf(v0.y * scv.y + shv.y, 0.0f);
        acc.z += n0 * fmaxf(v0.z * scv.z + shv.z, 0.0f);
        acc.w += n0 * fmaxf(v0.w * scv.w + shv.w, 0.0f);
    }
    ((float4*)out)[(size_t)node * 32 + lane] = acc;
}

// ---------------------------------------------------------------------------
// GEMM (fp32 f32x2): 256 threads, 64 rows/block, 2-col thread tile.
// ---------------------------------------------------------------------------
template <int K>
__global__ __launch_bounds__(256) void gemm_kernel(const float* __restrict__ A,
                                                   const float* __restrict__ Wp,
                                                   const float* __restrict__ b,
                                                   float* __restrict__ C,
                                                   float* __restrict__ stats) {
    __shared__ float xs[GROWS][K];
    const int row0 = blockIdx.x * GROWS;
    const int tid = threadIdx.x;
    const int c = tid & 63;
    const int g = tid >> 6;            // 0..3

    float4* xs4 = (float4*)&xs[0][0];
    if (row0 + GROWS <= NNODES) {
        const float4* A4 = (const float4*)(A + (size_t)row0 * K);
#pragma unroll
        for (int i = tid; i < GROWS * K / 4; i += 256) xs4[i] = A4[i];
    } else {
        const float4* A4 = (const float4*)A;
#pragma unroll 1
        for (int i = tid; i < GROWS * K / 4; i += 256) {
            int r = i / (K / 4);
            int c4 = i % (K / 4);
            int row = min(row0 + r, NNODES - 1);
            xs4[i] = A4[(size_t)row * (K / 4) + c4];
        }
    }
    __syncthreads();

    ull acc0[16], acc1[16];
#pragma unroll
    for (int r = 0; r < 16; r++) { acc0[r] = 0ULL; acc1[r] = 0ULL; }

    const ulonglong2* Wp2 = (const ulonglong2*)Wp;
#pragma unroll 2
    for (int kp2 = 0; kp2 < K / 4; kp2++) {
        ulonglong2 w0 = Wp2[kp2 * CH + c];
        ulonglong2 w1 = Wp2[kp2 * CH + c + 64];
#pragma unroll
        for (int r = 0; r < 16; r++) {
            ulonglong2 xv = *(const ulonglong2*)&xs[g * 16 + r][4 * kp2];
            acc0[r] = ffma2(xv.x, w0.x, acc0[r]);
            acc0[r] = ffma2(xv.y, w0.y, acc0[r]);
            acc1[r] = ffma2(xv.x, w1.x, acc1[r]);
            acc1[r] = ffma2(xv.y, w1.y, acc1[r]);
        }
    }

    float b0 = b[c], b1 = b[c + 64];
    float s0 = 0.0f, q0 = 0.0f, s1 = 0.0f, q1 = 0.0f;
    const int rbase = row0 + g * 16;
#pragma unroll
    for (int r = 0; r < 16; r++) {
        if (rbase + r < NNODES) {
            float v0 = unpack_sum(acc0[r]) + b0;
            float v1 = unpack_sum(acc1[r]) + b1;
            C[(size_t)(rbase + r) * CH + c] = v0;
            C[(size_t)(rbase + r) * CH + c + 64] = v1;
            s0 += v0; q0 += v0 * v0;
            s1 += v1; q1 += v1 * v1;
        }
    }
    atomicAdd(&stats[c], s0);
    atomicAdd(&stats[CH + c], q0);
    atomicAdd(&stats[c + 64], s1);
    atomicAdd(&stats[CH + c + 64], q1);
}

// ---------------------------------------------------------------------------
// Final fused layer, TF32 tensor cores.
// 8 warps: warp -> row group rg=warp>>1 (16 rows), col half chf=warp&1 (64 cols).
// cs smem [GROWS][KS] padded to KS=388 for conflict-free A fragments.
// ---------------------------------------------------------------------------
__global__ __launch_bounds__(256) void final_tc_kernel(const float* __restrict__ h,
                                                       const float* __restrict__ dist,
                                                       const float* __restrict__ degf,
                                                       const float* __restrict__ Wd,
                                                       const float* __restrict__ bd,
                                                       const float* __restrict__ Wg,
                                                       const float* __restrict__ bg,
                                                       const unsigned* __restrict__ Wtc,
                                                       const float* __restrict__ bm,
                                                       const float* __restrict__ gamma,
                                                       const float* __restrict__ beta,
                                                       float* __restrict__ out) {
    extern __shared__ float smem[];
    float* cs = smem;                       // [GROWS][KS]
    float* sc = smem + GROWS * KS;
    float* sh = sc + CH;
    const int row0 = blockIdx.x * GROWS;
    const int tid = threadIdx.x;

    if (tid < CH) {
        float mean = g_stats[2 * CH + tid] * (1.0f / NNODES);
        float var = g_stats[3 * CH + tid] * (1.0f / NNODES) - mean * mean;
        float scale = gamma[tid] * rsqrtf(var + 1e-5f);
        sc[tid] = scale;
        sh[tid] = beta[tid] - mean * scale;
    }
    __syncthreads();

    // Fill cs: [0:128) = relu(bn2(h2)), [128:256) dist feat, [256:384) deg feat
    const float4* h4 = (const float4*)h;
#pragma unroll 1
    for (int i = tid; i < GROWS * CH / 4; i += 256) {
        int r = i >> 5;
        int cc = (i & 31) * 4;
        int row = min(row0 + r, NNODES - 1);
        float4 v = h4[(size_t)row * 32 + (i & 31)];
        float4 scv = *(const float4*)&sc[cc];
        float4 shv = *(const float4*)&sh[cc];
        v.x = fmaxf(v.x * scv.x + shv.x, 0.0f);
        v.y = fmaxf(v.y * scv.y + shv.y, 0.0f);
        v.z = fmaxf(v.z * scv.z + shv.z, 0.0f);
        v.w = fmaxf(v.w * scv.w + shv.w, 0.0f);
        *(float4*)&cs[r * KS + cc] = v;
    }
    if (tid < 128) {
        float wd = Wd[tid], bdv = bd[tid];
#pragma unroll 4
        for (int r = 0; r < GROWS; r++) {
            int row = min(row0 + r, NNODES - 1);
            cs[r * KS + CH + tid] = fmaxf(dist[row] * wd + bdv, 0.0f);
        }
    } else {
        int c2 = tid - 128;
        float wg = Wg[c2], bgv = bg[c2];
#pragma unroll 4
        for (int r = 0; r < GROWS; r++) {
            int row = min(row0 + r, NNODES - 1);
            cs[r * KS + 2 * CH + c2] = fmaxf(degf[row] * wg + bgv, 0.0f);
        }
    }
    __syncthreads();

    const int warp = tid >> 5;
    const int lane = tid & 31;
    const int rg = warp >> 1;          // 0..3  -> rows [16rg, 16rg+16)
    const int chf = warp & 1;          // 0..1  -> cols [64chf, 64chf+64)
    const int r0 = lane >> 2;          // 0..7
    const int c0 = lane & 3;           // 0..3

    float acc[8][4];
#pragma unroll
    for (int nt = 0; nt < 8; nt++)
#pragma unroll
        for (int i = 0; i < 4; i++) acc[nt][i] = 0.0f;

    const float* a_lo = &cs[(16 * rg + r0) * KS];
    const float* a_hi = a_lo + 8 * KS;

#pragma unroll 4
    for (int kt = 0; kt < KFIN / 8; kt++) {
        int col = kt * 8 + c0;
        unsigned a0 = cvt_tf32(a_lo[col]);
        unsigned a1 = cvt_tf32(a_hi[col]);
        unsigned a2 = cvt_tf32(a_lo[col + 4]);
        unsigned a3 = cvt_tf32(a_hi[col + 4]);
        const uint2* wrow = (const uint2*)(Wtc + (size_t)(kt * 16 + chf * 8) * 64) + lane;
#pragma unroll
        for (int nt = 0; nt < 8; nt++) {
            uint2 b = wrow[nt * 32];
            mma_tf32(acc[nt], a0, a1, a2, a3, b.x, b.y);
        }
    }

    // Epilogue: D frag rows r0 / r0+8, cols 2*(lane%4)+{0,1} within n-tile
    const int ra = row0 + 16 * rg + r0;
    const int rb = ra + 8;
#pragma unroll
    for (int nt = 0; nt < 8; nt++) {
        int c = chf * 64 + nt * 8 + c0 * 2;
        float bm0 = bm[c], bm1 = bm[c + 1];
        if (ra < NNODES) {
            out[(size_t)ra * CH + c] = acc[nt][0] + bm0;
            out[(size_t)ra * CH + c + 1] = acc[nt][1] + bm1;
        }
        if (rb < NNODES) {
            out[(size_t)rb * CH + c] = acc[nt][2] + bm0;
            out[(size_t)rb * CH + c + 1] = acc[nt][3] + bm1;
        }
    }
}

// ---------------------------------------------------------------------------
extern "C" void kernel_launch(void* const* d_in, const int* in_sizes, int n_in,
                              void* d_out, int out_size) {
    const float* x     = (const float*)d_in[0];
    const void*  ei    = d_in[1];
    const float* ew    = (const float*)d_in[2];
    const float* dist  = (const float*)d_in[3];
    const float* degf  = (const float*)d_in[4];
    const float* W1    = (const float*)d_in[5];
    const float* b1    = (const float*)d_in[6];
    const float* W2    = (const float*)d_in[7];
    const float* b2    = (const float*)d_in[8];
    const float* g1    = (const float*)d_in[9];
    const float* be1   = (const float*)d_in[10];
    const float* g2    = (const float*)d_in[11];
    const float* be2   = (const float*)d_in[12];
    const float* Wd    = (const float*)d_in[13];
    const float* bd    = (const float*)d_in[14];
    const float* Wg    = (const float*)d_in[15];
    const float* bg    = (const float*)d_in[16];
    const float* Wm    = (const float*)d_in[17];
    const float* bm    = (const float*)d_in[18];
    float* out = (float*)d_out;

    float *bufA, *bufB, *stats, *Wp1, *Wp2;
    unsigned* Wtc;
    cudaGetSymbolAddress((void**)&bufA, g_bufA);
    cudaGetSymbolAddress((void**)&bufB, g_bufB);
    cudaGetSymbolAddress((void**)&stats, g_stats);
    cudaGetSymbolAddress((void**)&Wp1, g_Wp1);
    cudaGetSymbolAddress((void**)&Wp2, g_Wp2);
    cudaGetSymbolAddress((void**)&Wtc, g_Wtc);

    const int nodeBlocks = (NNODES + 255) / 256;
    const int edgeBlocks = (NEDGES + 255) / 256;
    const int gemmBlocks = (NNODES + GROWS - 1) / GROWS;   // 1563
    const int agg128Blocks = (NNODES * 32 + 255) / 256;
    const int agg64Blocks  = ((NNODES + 1) / 2 * 32 + 255) / 256;
    const int FIN_SMEM = (GROWS * KS + 2 * CH) * 4;        // 100352 B

    cudaFuncSetAttribute(final_tc_kernel, cudaFuncAttributeMaxDynamicSharedMemorySize, FIN_SMEM);

    // slots 1-3
    detect_idx_kernel<<<1, 256>>>((const int*)ei);
    deg_init_kernel<<<nodeBlocks, 256>>>();
    pack_kernel<<<160, 256>>>(W1, W2, Wm);

    // slot 4: ncu PROBE of final_tc_kernel (grid-limited, saturating; out overwritten)
    final_tc_kernel<<<600, 256, FIN_SMEM>>>(bufB, dist, degf, Wd, bd, Wg, bg,
                                            Wtc, bm, g2, be2, out);

    // --- gcn_norm + CSR build ---
    deg_count_kernel<<<edgeBlocks, 256>>>(ei, ew);
    scanA_kernel<<<SCAN_BLOCKS, SCAN_BT>>>();
    scanB_kernel<<<1, 256>>>();
    scanC_kernel<<<SCAN_BLOCKS, SCAN_BT>>>();
    fill_kernel<<<edgeBlocks, 256>>>(ei, ew);

    // --- layer 1 ---
    agg64_kernel<<<agg64Blocks, 256>>>(x, bufA);
    gemm_kernel<CIN><<<gemmBlocks, 256>>>(bufA, Wp1, b1, bufB, stats);

    // --- layer 2 ---
    agg_bn_kernel<<<agg128Blocks, 256>>>(bufB, g1, be1, bufA);
    gemm_kernel<CH><<<gemmBlocks, 256>>>(bufA, Wp2, b2, bufB, stats + 2 * CH);

    // --- final (TF32 tensor cores) ---
    final_tc_kernel<<<gemmBlocks, 256, FIN_SMEM>>>(bufB, dist, degf, Wd, bd, Wg, bg,
                                                   Wtc, bm, g2, be2, out);
}